// round 16
// baseline (speedup 1.0000x reference)
#include <cuda_runtime.h>
#include <cuda_bf16.h>

// EdgeAtt: B=64, L=512, D=512. Three-stage pipeline:
//  k_proj   : projections (DRAM reads) + zero rows (L2 stores) overlapped
//  k_sum    : lane-per-row row sums (no warp reduces) -> per-row constants
//             (E1/s, E2/s, T) + per-batch tables f1,f2 (exp factorization)
//  k_stream : pure store stream, per element (f1>T ? f1*E1s : f2*E2s)

#define L_DIM 512
#define D_DIM 512
#define SLOPE 0.2f
#define MASKV -1e9f

__device__ float  g_ei[64 * L_DIM];
__device__ float  g_ej[64 * L_DIM];
__device__ float  g_f1[64 * L_DIM];
__device__ float  g_f2[64 * L_DIM];
__device__ float4 g_c [64 * L_DIM];   // (E1/s, E2/s, T, unused) per row

// ---------------- kernel 1: projection + zero rows ----------------
__global__ void __launch_bounds__(256) k_proj(const float* __restrict__ nf,
                                              const float* __restrict__ wa,
                                              const int* __restrict__ tlen,
                                              float* __restrict__ out) {
    cudaTriggerProgrammaticLaunchCompletion();

    const int tid  = threadIdx.x;
    const int warp = tid >> 5;
    const int lane = tid & 31;
    const int r    = blockIdx.x * 8 + warp;      // global row
    const int b    = r >> 9;
    const int l    = r & (L_DIM - 1);
    const int len  = __ldg(&tlen[b]);

    if (l < len) {
        const float4* row = reinterpret_cast<const float4*>(nf + (size_t)r * D_DIM);
        const float4* w1  = reinterpret_cast<const float4*>(wa);
        const float4* w2  = reinterpret_cast<const float4*>(wa + D_DIM);
        float s1 = 0.f, s2 = 0.f;
#pragma unroll
        for (int t = 0; t < 4; t++) {
            int idx = lane + t * 32;
            float4 v = row[idx];
            float4 a = __ldg(&w1[idx]);
            float4 w = __ldg(&w2[idx]);
            s1 += v.x * a.x + v.y * a.y + v.z * a.z + v.w * a.w;
            s2 += v.x * w.x + v.y * w.y + v.z * w.z + v.w * w.w;
        }
#pragma unroll
        for (int o = 16; o; o >>= 1) {
            s1 += __shfl_xor_sync(0xffffffffu, s1, o);
            s2 += __shfl_xor_sync(0xffffffffu, s2, o);
        }
        if (lane == 0) { g_ei[r] = s1; g_ej[r] = s2; }
    } else {
        float4* orow4 = reinterpret_cast<float4*>(out + (size_t)r * L_DIM);
        float4 z = make_float4(0.f, 0.f, 0.f, 0.f);
#pragma unroll
        for (int t = 0; t < 4; t++) orow4[t * 32 + lane] = z;
    }
}

// ---------------- kernel 2: row sums, lane-per-row ----------------
// grid 128: CTA (b, half). Each warp owns 32 rows (lane = row). No per-row
// reduces: each lane accumulates its own row's softmax denominator.
__global__ void __launch_bounds__(256) k_sum(const float* __restrict__ ba,
                                             const int* __restrict__ tlen) {
    __shared__ float sej[L_DIM];
    __shared__ float smax[8];

    const int b    = blockIdx.x >> 1;
    const int half = blockIdx.x & 1;
    const int tid  = threadIdx.x;
    const int warp = tid >> 5;
    const int lane = tid & 31;
    const int len  = __ldg(&tlen[b]);

    cudaTriggerProgrammaticLaunchCompletion();   // let k_stream dispatch
    cudaGridDependencySynchronize();             // wait for k_proj

    // premasked e_j (masked -> -1e9 -> exp underflows to exact 0)
    const float v0 = (tid       < len) ? g_ej[b * L_DIM + tid]       : MASKV;
    const float v1 = (tid + 256 < len) ? g_ej[b * L_DIM + tid + 256] : MASKV;
    sej[tid]       = v0;
    sej[tid + 256] = v1;

    float mv = fmaxf(v0, v1);
#pragma unroll
    for (int o = 16; o; o >>= 1) mv = fmaxf(mv, __shfl_xor_sync(0xffffffffu, mv, o));
    if (lane == 0) smax[warp] = mv;
    __syncthreads();
    float mxej = smax[0];
#pragma unroll
    for (int k = 1; k < 8; k++) mxej = fmaxf(mxej, smax[k]);

    // per-batch factorization tables (one CTA per batch writes)
    if (half == 0) {
        g_f1[b * L_DIM + tid]       = __expf(v0 - mxej);
        g_f1[b * L_DIM + tid + 256] = __expf(v1 - mxej);
        g_f2[b * L_DIM + tid]       = __expf(SLOPE * (v0 - mxej));
        g_f2[b * L_DIM + tid + 256] = __expf(SLOPE * (v1 - mxej));
    }

    const int row = half * 256 + warp * 32 + lane;   // this lane's row
    if (row >= len) return;                          // no sum needed

    const float ei   = g_ei[b * L_DIM + row] + __ldg(ba);
    const float mraw = ei + mxej;
    const float m    = fmaxf(mraw, SLOPE * mraw);    // exact row max

    const int nt = (len + 127) >> 7;                 // live tiles
    const float4* sej4 = reinterpret_cast<const float4*>(sej);

    float sa = 0.f, sb = 0.f;                        // 2 accumulators
    for (int jg = 0; jg < nt * 32; jg++) {           // broadcast LDS.128
        float4 e4 = sej4[jg];
        float v, lr;
        v = ei + e4.x; lr = fmaxf(v, SLOPE * v); sa += __expf(lr - m);
        v = ei + e4.y; lr = fmaxf(v, SLOPE * v); sb += __expf(lr - m);
        v = ei + e4.z; lr = fmaxf(v, SLOPE * v); sa += __expf(lr - m);
        v = ei + e4.w; lr = fmaxf(v, SLOPE * v); sb += __expf(lr - m);
    }
    const float inv = __fdividef(1.f, sa + sb);

    float4 c;
    c.x = __expf(mraw - m) * inv;            // E1/s
    c.y = __expf(SLOPE * mraw - m) * inv;    // E2/s
    c.z = __expf(-mraw);                     // T: f1 > T <=> ei+ej > 0
    c.w = 0.f;
    g_c[b * L_DIM + row] = c;                // coalesced float4 across lanes
}

// ---------------- kernel 3: streaming stores, warp per row ----------------
__global__ void __launch_bounds__(256) k_stream(const int* __restrict__ tlen,
                                                float* __restrict__ out) {
    __shared__ float4 sf1[L_DIM / 4];
    __shared__ float4 sf2[L_DIM / 4];

    const int b    = blockIdx.y;
    const int tid  = threadIdx.x;
    const int warp = tid >> 5;
    const int lane = tid & 31;
    const int len  = __ldg(&tlen[b]);

    if ((int)blockIdx.x * 8 >= len) return;  // zeros already written by k_proj

    cudaGridDependencySynchronize();         // wait for k_sum

    // cooperative table load (256 threads, 256 float4s total)
    const float4* gf14 = reinterpret_cast<const float4*>(g_f1 + b * L_DIM);
    const float4* gf24 = reinterpret_cast<const float4*>(g_f2 + b * L_DIM);
    if (tid < 128) sf1[tid] = __ldg(&gf14[tid]);
    else           sf2[tid - 128] = __ldg(&gf24[tid - 128]);
    __syncthreads();

    const int i = blockIdx.x * 8 + warp;
    if (i >= len) return;                    // zero row written by k_proj

    const float4 c = __ldg(&g_c[b * L_DIM + i]);   // E1s, E2s, T
    const int nt = (len + 127) >> 7;

    float4* orow4 = reinterpret_cast<float4*>(out + ((size_t)b * L_DIM + i) * L_DIM);
#pragma unroll
    for (int t = 0; t < 4; t++) {
        float4 r;
        if (t < nt) {
            float4 f1 = sf1[t * 32 + lane];
            float4 f2 = sf2[t * 32 + lane];
            r.x = (f1.x > c.z) ? f1.x * c.x : f2.x * c.y;
            r.y = (f1.y > c.z) ? f1.y * c.x : f2.y * c.y;
            r.z = (f1.z > c.z) ? f1.z * c.x : f2.z * c.y;
            r.w = (f1.w > c.z) ? f1.w * c.x : f2.w * c.y;
        } else {
            r = make_float4(0.f, 0.f, 0.f, 0.f);
        }
        orow4[t * 32 + lane] = r;
    }
}

extern "C" void kernel_launch(void* const* d_in, const int* in_sizes, int n_in,
                              void* d_out, int out_size) {
    const float* nf   = (const float*)d_in[0];   // [B, L, D]
    const float* wa   = (const float*)d_in[1];   // [2D]
    const float* ba   = (const float*)d_in[2];   // [1]
    const int*   tlen = (const int*)d_in[3];     // [B]
    float* out = (float*)d_out;                  // [B, L, L]

    const int B = in_sizes[3];

    k_proj<<<B * L_DIM / 8, 256>>>(nf, wa, tlen, out);

    cudaLaunchAttribute attr[1];
    attr[0].id = cudaLaunchAttributeProgrammaticStreamSerialization;
    attr[0].val.programmaticStreamSerializationAllowed = 1;

    cudaLaunchConfig_t cfg1 = {};
    cfg1.gridDim  = dim3((unsigned)B * 2, 1, 1);
    cfg1.blockDim = dim3(256, 1, 1);
    cfg1.stream = 0;
    cfg1.attrs = attr;
    cfg1.numAttrs = 1;
    cudaLaunchKernelEx(&cfg1, k_sum, ba, tlen);

    cudaLaunchConfig_t cfg2 = {};
    cfg2.gridDim  = dim3(L_DIM / 8, (unsigned)B, 1);
    cfg2.blockDim = dim3(256, 1, 1);
    cfg2.stream = 0;
    cfg2.attrs = attr;
    cfg2.numAttrs = 1;
    cudaLaunchKernelEx(&cfg2, k_stream, tlen, out);
}

// round 17
// speedup vs baseline: 1.4951x; 1.4951x over previous
#include <cuda_runtime.h>
#include <cuda_bf16.h>

// EdgeAtt: B=64, L=512, D=512.
// k_proj: warp/row; valid rows project (DRAM reads), invalid rows write
// their zero output row (L2 stores) — streams overlap in one kernel.
// k_soft: warp-autonomous, 4 rows/warp processed as 2 interleaved pairs
// (ILP 2 on the exp chains + shuffle reduces). Column skip for dead tiles.

#define L_DIM 512
#define D_DIM 512
#define SLOPE 0.2f
#define MASKV -1e9f

__device__ float g_ei[64 * L_DIM];
__device__ float g_ej[64 * L_DIM];

// ---------------- kernel 1: projection + zero rows ----------------
__global__ void __launch_bounds__(256) k_proj(const float* __restrict__ nf,
                                              const float* __restrict__ wa,
                                              const int* __restrict__ tlen,
                                              float* __restrict__ out) {
    cudaTriggerProgrammaticLaunchCompletion();

    const int tid  = threadIdx.x;
    const int warp = tid >> 5;
    const int lane = tid & 31;
    const int r    = blockIdx.x * 8 + warp;      // global row
    const int b    = r >> 9;
    const int l    = r & (L_DIM - 1);
    const int len  = __ldg(&tlen[b]);

    if (l < len) {
        const float4* row = reinterpret_cast<const float4*>(nf + (size_t)r * D_DIM);
        const float4* w1  = reinterpret_cast<const float4*>(wa);
        const float4* w2  = reinterpret_cast<const float4*>(wa + D_DIM);

        float s1 = 0.f, s2 = 0.f;
#pragma unroll
        for (int t = 0; t < 4; t++) {
            int idx = lane + t * 32;
            float4 v = row[idx];
            float4 a = __ldg(&w1[idx]);
            float4 w = __ldg(&w2[idx]);
            s1 += v.x * a.x + v.y * a.y + v.z * a.z + v.w * a.w;
            s2 += v.x * w.x + v.y * w.y + v.z * w.z + v.w * w.w;
        }
#pragma unroll
        for (int o = 16; o; o >>= 1) {
            s1 += __shfl_xor_sync(0xffffffffu, s1, o);
            s2 += __shfl_xor_sync(0xffffffffu, s2, o);
        }
        if (lane == 0) { g_ei[r] = s1; g_ej[r] = s2; }
    } else {
        float4* orow4 = reinterpret_cast<float4*>(out + (size_t)r * L_DIM);
        float4 z = make_float4(0.f, 0.f, 0.f, 0.f);
#pragma unroll
        for (int t = 0; t < 4; t++) orow4[t * 32 + lane] = z;
    }
}

// ---------------- kernel 2: warp-autonomous softmax, paired rows ----------------
// grid (L/32, B), block 256: warp w handles rows bx*32 + w*4 .. +3 in 2 pairs.
__global__ void __launch_bounds__(256) k_soft(const float* __restrict__ ba,
                                              const int* __restrict__ tlen,
                                              float* __restrict__ out) {
    const int b    = blockIdx.y;
    const int tid  = threadIdx.x;
    const int warp = tid >> 5;
    const int lane = tid & 31;
    const int len  = __ldg(&tlen[b]);            // input only: no dependency

    if ((int)blockIdx.x * 32 >= len) return;     // zeros written by k_proj

    cudaGridDependencySynchronize();

    const int nt = (len + 127) >> 7;             // live tiles (1..4), uniform
    const float4* ej4 = reinterpret_cast<const float4*>(g_ej + b * L_DIM);

    // all premasked e_j in registers (<= 4 coalesced LDG.128)
    float4 e[4];
    float mv = MASKV;
#pragma unroll
    for (int t = 0; t < 4; t++) {
        if (t < nt) {
            const int j0 = t * 128 + lane * 4;
            float4 v = __ldg(&ej4[t * 32 + lane]);
            const int rem = len - j0;
            v.x = (0 < rem) ? v.x : MASKV;
            v.y = (1 < rem) ? v.y : MASKV;
            v.z = (2 < rem) ? v.z : MASKV;
            v.w = (3 < rem) ? v.w : MASKV;
            e[t] = v;
            mv = fmaxf(mv, fmaxf(fmaxf(v.x, v.y), fmaxf(v.z, v.w)));
        }
    }
#pragma unroll
    for (int o = 16; o; o >>= 1) mv = fmaxf(mv, __shfl_xor_sync(0xffffffffu, mv, o));
    const float mxej = mv;

    const float bias = __ldg(ba);
    const int row0 = blockIdx.x * 32 + warp * 4;

#pragma unroll
    for (int rp = 0; rp < 4; rp += 2) {
        const int i0 = row0 + rp;
        const int i1 = row0 + rp + 1;
        if (i0 >= len) break;
        const bool a1 = (i1 < len);

        const float ei0 = __ldg(&g_ei[b * L_DIM + i0]) + bias;
        const float ei1 = a1 ? (__ldg(&g_ei[b * L_DIM + i1]) + bias) : ei0;
        const float mr0 = ei0 + mxej, mr1 = ei1 + mxej;
        const float m0 = fmaxf(mr0, SLOPE * mr0);
        const float m1 = fmaxf(mr1, SLOPE * mr1);

        float4 p0[4], p1[4];
        float s0 = 0.f, s1 = 0.f;
#pragma unroll
        for (int t = 0; t < 4; t++) {
            if (t < nt) {
                float v0, v1, l0, l1, q0, q1;
                v0 = ei0 + e[t].x; v1 = ei1 + e[t].x;
                l0 = fmaxf(v0, SLOPE * v0); l1 = fmaxf(v1, SLOPE * v1);
                q0 = __expf(l0 - m0); q1 = __expf(l1 - m1);
                p0[t].x = q0; s0 += q0; p1[t].x = q1; s1 += q1;

                v0 = ei0 + e[t].y; v1 = ei1 + e[t].y;
                l0 = fmaxf(v0, SLOPE * v0); l1 = fmaxf(v1, SLOPE * v1);
                q0 = __expf(l0 - m0); q1 = __expf(l1 - m1);
                p0[t].y = q0; s0 += q0; p1[t].y = q1; s1 += q1;

                v0 = ei0 + e[t].z; v1 = ei1 + e[t].z;
                l0 = fmaxf(v0, SLOPE * v0); l1 = fmaxf(v1, SLOPE * v1);
                q0 = __expf(l0 - m0); q1 = __expf(l1 - m1);
                p0[t].z = q0; s0 += q0; p1[t].z = q1; s1 += q1;

                v0 = ei0 + e[t].w; v1 = ei1 + e[t].w;
                l0 = fmaxf(v0, SLOPE * v0); l1 = fmaxf(v1, SLOPE * v1);
                q0 = __expf(l0 - m0); q1 = __expf(l1 - m1);
                p0[t].w = q0; s0 += q0; p1[t].w = q1; s1 += q1;
            }
        }
        // interleaved reduces: the two chains pipeline
#pragma unroll
        for (int o = 16; o; o >>= 1) {
            s0 += __shfl_xor_sync(0xffffffffu, s0, o);
            s1 += __shfl_xor_sync(0xffffffffu, s1, o);
        }
        const float inv0 = 1.f / s0;
        const float inv1 = 1.f / s1;

        float4* or0 = reinterpret_cast<float4*>(out + ((size_t)b * L_DIM + i0) * L_DIM);
        float4* or1 = reinterpret_cast<float4*>(out + ((size_t)b * L_DIM + i1) * L_DIM);
#pragma unroll
        for (int t = 0; t < 4; t++) {
            float4 r0, r1;
            if (t < nt) {
                r0.x = p0[t].x * inv0; r0.y = p0[t].y * inv0;
                r0.z = p0[t].z * inv0; r0.w = p0[t].w * inv0;
                r1.x = p1[t].x * inv1; r1.y = p1[t].y * inv1;
                r1.z = p1[t].z * inv1; r1.w = p1[t].w * inv1;
            } else {
                r0 = make_float4(0.f, 0.f, 0.f, 0.f);
                r1 = r0;
            }
            or0[t * 32 + lane] = r0;
            if (a1) or1[t * 32 + lane] = r1;
        }
    }
}

extern "C" void kernel_launch(void* const* d_in, const int* in_sizes, int n_in,
                              void* d_out, int out_size) {
    const float* nf   = (const float*)d_in[0];   // [B, L, D]
    const float* wa   = (const float*)d_in[1];   // [2D]
    const float* ba   = (const float*)d_in[2];   // [1]
    const int*   tlen = (const int*)d_in[3];     // [B]
    float* out = (float*)d_out;                  // [B, L, L]

    const int B = in_sizes[3];

    k_proj<<<B * L_DIM / 8, 256>>>(nf, wa, tlen, out);

    cudaLaunchConfig_t cfg = {};
    cfg.gridDim  = dim3(L_DIM / 32, (unsigned)B, 1);
    cfg.blockDim = dim3(256, 1, 1);
    cfg.dynamicSmemBytes = 0;
    cfg.stream = 0;
    cudaLaunchAttribute attr[1];
    attr[0].id = cudaLaunchAttributeProgrammaticStreamSerialization;
    attr[0].val.programmaticStreamSerializationAllowed = 1;
    cfg.attrs = attr;
    cfg.numAttrs = 1;
    cudaLaunchKernelEx(&cfg, k_soft, ba, tlen, out);
}